// round 16
// baseline (speedup 1.0000x reference)
#include <cuda_runtime.h>
#include <cuda_fp16.h>
#include <cstdint>

// ---------------- problem constants ----------------
#define N_IN   200000
#define N_OUT  100000
#define NE     1600000
#define CIN    64
#define CO     128
#define KHALF  576
#define MTILE  128
#define MPAD   100096          // 782 * 128
#define NTILES 782
#define KCH    32              // K elems per pipeline chunk
#define NCHUNK 18              // 576 / 32
#define STAGE  32768           // 4 arrays x [128][32] fp16 (8KB each)

#define ASZ    ((size_t)MPAD * KHALF)
#define BSZ    ((size_t)CO * KHALF)

// ---------------- device scratch (no allocs allowed) ----------------
__device__ int       g_offs[N_OUT + 1];
__device__ int       g_koffs[(size_t)N_OUT * 10];  // per-(point,k) group bounds
__device__ float     g_imp[N_OUT];
__device__ int2      g_edges[NE];             // k-sorted {src<<4|k, imp}
// A arrays (fp16): 0=Au 1=Aw ; never-written bins stay zero (.bss)
__device__ __half    g_A[2][ASZ];
// B arrays (fp16): 0=Bh 1=Bl  (row-major [o][k])
__device__ __half    g_B[2][BSZ];

// ---------------- helpers ----------------
__device__ __forceinline__ uint32_t smem_u32(const void* p) {
    uint32_t a;
    asm("{ .reg .u64 t; cvta.to.shared.u64 t, %1; cvt.u32.u64 %0, t; }"
        : "=r"(a) : "l"(p));
    return a;
}
__device__ __forceinline__ uint32_t sw64(uint32_t o) {   // 64B-row swizzle
    return o ^ ((o >> 3) & 0x30);
}
__device__ __forceinline__ void cp16(uint32_t dst, const void* src) {
    asm volatile("cp.async.cg.shared.global [%0], [%1], 16;" :: "r"(dst), "l"(src));
}
#define CP_COMMIT asm volatile("cp.async.commit_group;" ::: "memory")

__device__ __forceinline__ void ldm4(uint32_t& r0, uint32_t& r1,
                                     uint32_t& r2, uint32_t& r3, uint32_t a) {
    asm volatile("ldmatrix.sync.aligned.m8n8.x4.shared.b16 {%0,%1,%2,%3}, [%4];"
                 : "=r"(r0), "=r"(r1), "=r"(r2), "=r"(r3) : "r"(a));
}
__device__ __forceinline__ void mma_f16(float* c, const uint32_t* a,
                                        uint32_t b0, uint32_t b1) {
    asm volatile(
        "mma.sync.aligned.m16n8k16.row.col.f32.f16.f16.f32 "
        "{%0,%1,%2,%3}, {%4,%5,%6,%7}, {%8,%9}, {%0,%1,%2,%3};"
        : "+f"(c[0]), "+f"(c[1]), "+f"(c[2]), "+f"(c[3])
        : "r"(a[0]), "r"(a[1]), "r"(a[2]), "r"(a[3]), "r"(b0), "r"(b1));
}

// ---------------------------------------------------------------------------
// Kernel 1: CSR offsets via adjacent-diff over sorted neighbors_out_index
// ---------------------------------------------------------------------------
__global__ void build_offsets_kernel(const int* __restrict__ out_idx) {
    int e = blockIdx.x * blockDim.x + threadIdx.x;
    if (e >= NE) return;
    int b = __ldg(out_idx + e);
    int a = (e == 0) ? -1 : __ldg(out_idx + e - 1);
    for (int n = a + 1; n <= b; n++) g_offs[n] = e;
    if (e == NE - 1)
        for (int n = b + 1; n <= N_OUT; n++) g_offs[n] = NE;
}

// ---------------------------------------------------------------------------
// Kernel 1b: WARP-PARALLEL per-point counting sort of edges by k.
// Also persists per-(point,k) group start offsets (g_koffs[n][0..9]).
// ---------------------------------------------------------------------------
__global__ __launch_bounds__(256)
void sort_edges_kernel(const int* __restrict__ nbr,
                       const int* __restrict__ kid,
                       const float* __restrict__ importance) {
    const int lane = threadIdx.x & 31;
    const int n    = blockIdx.x * 8 + (threadIdx.x >> 5);
    const int e0 = g_offs[n], e1 = g_offs[n + 1];
    const uint32_t ltmask = (1u << lane) - 1u;

    int off[9];
    #pragma unroll
    for (int kk = 0; kk < 9; kk++) off[kk] = 0;

    for (int base = e0; base < e1; base += 32) {
        const int e = base + lane;
        const int k = (e < e1) ? __ldg(kid + e) : 15;
        #pragma unroll
        for (int kk = 0; kk < 9; kk++)
            off[kk] += __popc(__ballot_sync(0xffffffffu, k == kk));
    }
    {
        int s = e0;
        #pragma unroll
        for (int kk = 0; kk < 9; kk++) { const int c = off[kk]; off[kk] = s; s += c; }
    }
    if (lane == 0) {
        int* ko = g_koffs + (size_t)n * 10;
        #pragma unroll
        for (int kk = 0; kk < 9; kk++) ko[kk] = off[kk];
        ko[9] = e1;
    }
    for (int base = e0; base < e1; base += 32) {
        const int e = base + lane;
        const bool valid = e < e1;
        const int k   = valid ? __ldg(kid + e) : 15;
        const int src = valid ? __ldg(nbr + e) : 0;
        int dst = 0;
        #pragma unroll
        for (int kk = 0; kk < 9; kk++) {
            const uint32_t m = __ballot_sync(0xffffffffu, k == kk);
            if (k == kk) dst = off[kk] + __popc(m & ltmask);
            off[kk] += __popc(m);
        }
        if (valid) {
            int2 r;
            r.x = (src << 4) | k;
            r.y = __float_as_int(__ldg(importance + src));
            g_edges[dst] = r;
        }
    }
}

// ---------------------------------------------------------------------------
// Kernel 2: compressed weights [128][576], fp16 hi + fp16 residual lo
// ---------------------------------------------------------------------------
__global__ void build_w_kernel(const float* __restrict__ Wa,
                               const float* __restrict__ Wb) {
    int i = blockIdx.x * blockDim.x + threadIdx.x;
    if (i >= CO * KHALF) return;
    int o = i / KHALF, k = i % KHALF;
    float v = (o < 96) ? __ldg(Wa + k * 96 + o) : __ldg(Wb + k * 32 + (o - 96));
    __half h = __float2half(v);
    g_B[0][i] = h;
    g_B[1][i] = __float2half(v - __half2float(h));
}

// ---------------------------------------------------------------------------
// Kernel 3: binning, ZERO smem, HALF-WARP per point (float4 channels).
// Lane li in [0,16) owns channels 4li..4li+3; each warp handles 2 points
// (one per half). k-group bounds from g_koffs keep k compile-time;
// accumulation order per channel identical to previous rounds.
// ---------------------------------------------------------------------------
__global__ __launch_bounds__(256)
void bin_kernel(const float* __restrict__ feats,
                float*       __restrict__ out) {
    const int lane = threadIdx.x & 31;
    const int hw   = lane >> 4;          // half-warp id: which point
    const int li   = lane & 15;          // lane within half
    const int n    = blockIdx.x * 16 + (threadIdx.x >> 5) * 2 + hw;
    const size_t rb = (size_t)n * KHALF;
    const int* ko = g_koffs + (size_t)n * 10;

    float impacc = 0.f;
    int start = __ldg(ko);
    #pragma unroll
    for (int kk = 0; kk < 9; kk++) {
        const int end = __ldg(ko + kk + 1);
        if (start < end) {
            float4 u = make_float4(0.f, 0.f, 0.f, 0.f);
            float4 w = make_float4(0.f, 0.f, 0.f, 0.f);
            for (int e = start; e < end; e++) {
                const int2  rec = __ldg(g_edges + e);    // broadcast in half
                const int   src = rec.x >> 4;
                const float im  = __int_as_float(rec.y);
                const float4 f  = *reinterpret_cast<const float4*>(
                                      feats + (size_t)src * CIN + 4 * li);
                u.x += f.x; u.y += f.y; u.z += f.z; u.w += f.w;
                w.x = fmaf(f.x, im, w.x); w.y = fmaf(f.y, im, w.y);
                w.z = fmaf(f.z, im, w.z); w.w = fmaf(f.w, im, w.w);
                impacc += im;
            }
            // flush: fp16x4 (8B) per lane per array, 128B coalesced per half
            const size_t off = rb + kk * 64 + 4 * li;
            __half2 u01 = __floats2half2_rn(u.x, u.y);
            __half2 u23 = __floats2half2_rn(u.z, u.w);
            __half2 w01 = __floats2half2_rn(w.x, w.y);
            __half2 w23 = __floats2half2_rn(w.z, w.w);
            uint2 uv, wv;
            uv.x = *reinterpret_cast<uint32_t*>(&u01);
            uv.y = *reinterpret_cast<uint32_t*>(&u23);
            wv.x = *reinterpret_cast<uint32_t*>(&w01);
            wv.y = *reinterpret_cast<uint32_t*>(&w23);
            *reinterpret_cast<uint2*>(&g_A[0][off]) = uv;
            *reinterpret_cast<uint2*>(&g_A[1][off]) = wv;
        }
        start = end;
    }

    if (li == 0) {
        g_imp[n] = impacc;
        out[(size_t)N_OUT * CO + n] = impacc;        // imp_sum output
    }
}

// ---------------------------------------------------------------------------
// Kernel 4: HMMA fp16 GEMM — round-14 config verbatim (measured ~111 us).
// 2 passes (A*Bh + A*Bl), 2 stages x 32KB, issue(c+1) before wait.
// Stage: [Au|Aw|Bh|Bl] x 8KB, 64B rows, sw64. 2 CTAs/SM.
// Warps 2(M64) x 4(N32); w_n<3 -> Au, w_n==3 -> Aw.
// ---------------------------------------------------------------------------
extern __shared__ __align__(128) char gsm[];

__global__ __launch_bounds__(256, 2)
void gemm_kernel(const float* __restrict__ b_a,
                 const float* __restrict__ b_b,
                 float*       __restrict__ out) {
    const int tid = threadIdx.x, lane = tid & 31, wid = tid >> 5;
    const int w_m = wid & 1, w_n = wid >> 1;
    const int g = lane >> 2, tig = lane & 3;
    const size_t mtile = (size_t)blockIdx.x * MTILE;
    const uint32_t sbase = smem_u32(gsm);

    // cp.async geometry: 2 x 16B per thread per array (128 rows x 4 cols)
    int   aIdx[2], bIdx[2];
    uint32_t dOff[2];
    #pragma unroll
    for (int q = 0; q < 2; q++) {
        const int idx = q * 256 + tid;      // 0..511
        const int row = idx >> 2, c = idx & 3;
        aIdx[q] = (int)((mtile + row) * KHALF + c * 8);
        bIdx[q] = row * KHALF + c * 8;
        dOff[q] = sw64(row * 64 + c * 16);
    }

    // ldmatrix per-lane base offsets, 64B rows
    const uint32_t aOffB = (uint32_t)(w_m * 64 + (lane & 15)) * 64
                         + ((lane >> 4) & 1) * 16;
    const uint32_t bOffB = (uint32_t)(w_n * 32 + (lane & 7) + ((lane >> 4) & 1) * 8) * 64
                         + ((lane >> 3) & 1) * 16;
    const uint32_t aSel = (w_n < 3) ? 0u : 8192u;   // Au vs Aw

    float acc[4][4][4];
    #pragma unroll
    for (int i = 0; i < 4; i++)
        #pragma unroll
        for (int j = 0; j < 4; j++)
            #pragma unroll
            for (int q = 0; q < 4; q++) acc[i][j][q] = 0.f;

    auto issue = [&](int c) {
        const uint32_t st = sbase + (uint32_t)(c & 1) * STAGE;
        const int k0 = c * KCH;
        #pragma unroll
        for (int q = 0; q < 2; q++) {
            #pragma unroll
            for (int arr = 0; arr < 2; arr++)
                cp16(st + arr * 8192 + dOff[q], &g_A[arr][0] + aIdx[q] + k0);
            #pragma unroll
            for (int arr = 0; arr < 2; arr++)
                cp16(st + 16384 + arr * 8192 + dOff[q], &g_B[arr][0] + bIdx[q] + k0);
        }
        CP_COMMIT;
    };

    issue(0);

    #pragma unroll 2
    for (int c = 0; c < NCHUNK; c++) {
        if (c + 1 < NCHUNK) {
            issue(c + 1);
            asm volatile("cp.async.wait_group 1;" ::: "memory");
        } else {
            asm volatile("cp.async.wait_group 0;" ::: "memory");
        }
        __syncthreads();

        const uint32_t st  = sbase + (uint32_t)(c & 1) * STAGE;
        const uint32_t sA  = st + aSel;
        const uint32_t sBh = st + 16384;
        const uint32_t sBl = st + 24576;

        #pragma unroll
        for (int ks = 0; ks < 2; ks++) {
            uint32_t bh[8], bl[8];
            ldm4(bh[0], bh[1], bh[2], bh[3], sBh + sw64(bOffB + ks * 32));
            ldm4(bh[4], bh[5], bh[6], bh[7], sBh + sw64(bOffB + 1024 + ks * 32));
            ldm4(bl[0], bl[1], bl[2], bl[3], sBl + sw64(bOffB + ks * 32));
            ldm4(bl[4], bl[5], bl[6], bl[7], sBl + sw64(bOffB + 1024 + ks * 32));
            #pragma unroll
            for (int mf = 0; mf < 4; mf++) {
                uint32_t ah[4];
                ldm4(ah[0], ah[1], ah[2], ah[3], sA + sw64(aOffB + mf * 1024 + ks * 32));
                #pragma unroll
                for (int nf = 0; nf < 4; nf++) {
                    mma_f16(acc[mf][nf], ah, bh[2 * nf], bh[2 * nf + 1]);
                    mma_f16(acc[mf][nf], ah, bl[2 * nf], bl[2 * nf + 1]);
                }
            }
        }
        __syncthreads();
    }

    // ---- epilogue: bias / normalize / relu / store ----
    float bias[4][2];
    #pragma unroll
    for (int nf = 0; nf < 4; nf++) {
        const int col = w_n * 32 + nf * 8 + 2 * tig;
        bias[nf][0] = (col < 96) ? __ldg(b_a + col)     : __ldg(b_b + col - 96);
        bias[nf][1] = (col < 96) ? __ldg(b_a + col + 1) : __ldg(b_b + col - 95);
    }

    #pragma unroll
    for (int mf = 0; mf < 4; mf++) {
        #pragma unroll
        for (int half = 0; half < 2; half++) {
            const int n = (int)mtile + w_m * 64 + mf * 16 + g + half * 8;
            if (n >= N_OUT) continue;
            float inv = 1.f;
            if (w_n == 3) inv = 1.f / fmaxf(__ldg(g_imp + n), 1e-8f);
            #pragma unroll
            for (int nf = 0; nf < 4; nf++) {
                const int col = w_n * 32 + nf * 8 + 2 * tig;
                float2 r;
                r.x = fmaxf(fmaf(acc[mf][nf][half * 2 + 0], inv, bias[nf][0]), 0.f);
                r.y = fmaxf(fmaf(acc[mf][nf][half * 2 + 1], inv, bias[nf][1]), 0.f);
                *reinterpret_cast<float2*>(out + (size_t)n * CO + col) = r;
            }
        }
    }
}

// ---------------------------------------------------------------------------
extern "C" void kernel_launch(void* const* d_in, const int* in_sizes, int n_in,
                              void* d_out, int out_size) {
    const float* feats      = (const float*)d_in[0];
    const float* importance = (const float*)d_in[1];
    const float* W_a        = (const float*)d_in[2];
    const float* b_a        = (const float*)d_in[3];
    const float* W_b        = (const float*)d_in[4];
    const float* b_b        = (const float*)d_in[5];
    const int*   nbr        = (const int*)d_in[6];
    const int*   kid        = (const int*)d_in[7];
    const int*   oid        = (const int*)d_in[8];
    float*       out        = (float*)d_out;

    build_offsets_kernel<<<(NE + 255) / 256, 256>>>(oid);
    sort_edges_kernel<<<N_OUT / 8, 256>>>(nbr, kid, importance);
    build_w_kernel<<<(CO * KHALF + 255) / 256, 256>>>(W_a, W_b);
    bin_kernel<<<N_OUT / 16, 256>>>(feats, out);

    const int smem_bytes = 2 * STAGE;   // 65,536 B -> 2 CTAs/SM
    cudaFuncSetAttribute(gemm_kernel,
                         cudaFuncAttributeMaxDynamicSharedMemorySize, smem_bytes);
    gemm_kernel<<<NTILES, 256, smem_bytes>>>(b_a, b_b, out);
}

// round 17
// speedup vs baseline: 1.2340x; 1.2340x over previous
#include <cuda_runtime.h>
#include <cuda_fp16.h>
#include <cstdint>

// ---------------- problem constants ----------------
#define N_IN   200000
#define N_OUT  100000
#define NE     1600000
#define CIN    64
#define CO     128
#define KHALF  576
#define MTILE  128
#define MPAD   100096          // 782 * 128
#define NTILES 782
#define KCH    32              // K elems per pipeline chunk
#define NCHUNK 18              // 576 / 32
#define STAGE  24576           // 3 arrays x [128][32] fp16 (8KB each)

#define ASZ    ((size_t)MPAD * KHALF)
#define BSZ    ((size_t)CO * KHALF)

// ---------------- device scratch (no allocs allowed) ----------------
__device__ int       g_offs[N_OUT + 1];
__device__ float     g_imp[N_OUT];
__device__ int2      g_edges[NE];             // k-sorted {src<<4|k, imp}
// A arrays (fp16): 0=Au 1=Aw ; never-written bins stay zero (.bss)
__device__ __half    g_A[2][ASZ];
// B (fp16, single precision level), row-major [o][k]
__device__ __half    g_B[BSZ];

// ---------------- helpers ----------------
__device__ __forceinline__ uint32_t smem_u32(const void* p) {
    uint32_t a;
    asm("{ .reg .u64 t; cvta.to.shared.u64 t, %1; cvt.u32.u64 %0, t; }"
        : "=r"(a) : "l"(p));
    return a;
}
__device__ __forceinline__ uint32_t sw64(uint32_t o) {   // 64B-row swizzle
    return o ^ ((o >> 3) & 0x30);
}
__device__ __forceinline__ void cp16(uint32_t dst, const void* src) {
    asm volatile("cp.async.cg.shared.global [%0], [%1], 16;" :: "r"(dst), "l"(src));
}
#define CP_COMMIT asm volatile("cp.async.commit_group;" ::: "memory")

__device__ __forceinline__ void ldm4(uint32_t& r0, uint32_t& r1,
                                     uint32_t& r2, uint32_t& r3, uint32_t a) {
    asm volatile("ldmatrix.sync.aligned.m8n8.x4.shared.b16 {%0,%1,%2,%3}, [%4];"
                 : "=r"(r0), "=r"(r1), "=r"(r2), "=r"(r3) : "r"(a));
}
__device__ __forceinline__ void mma_f16(float* c, const uint32_t* a,
                                        uint32_t b0, uint32_t b1) {
    asm volatile(
        "mma.sync.aligned.m16n8k16.row.col.f32.f16.f16.f32 "
        "{%0,%1,%2,%3}, {%4,%5,%6,%7}, {%8,%9}, {%0,%1,%2,%3};"
        : "+f"(c[0]), "+f"(c[1]), "+f"(c[2]), "+f"(c[3])
        : "r"(a[0]), "r"(a[1]), "r"(a[2]), "r"(a[3]), "r"(b0), "r"(b1));
}

// ---------------------------------------------------------------------------
// Kernel 1: CSR offsets via adjacent-diff over sorted neighbors_out_index
// ---------------------------------------------------------------------------
__global__ void build_offsets_kernel(const int* __restrict__ out_idx) {
    int e = blockIdx.x * blockDim.x + threadIdx.x;
    if (e >= NE) return;
    int b = __ldg(out_idx + e);
    int a = (e == 0) ? -1 : __ldg(out_idx + e - 1);
    for (int n = a + 1; n <= b; n++) g_offs[n] = e;
    if (e == NE - 1)
        for (int n = b + 1; n <= N_OUT; n++) g_offs[n] = NE;
}

// ---------------------------------------------------------------------------
// Kernel 1b: WARP-PARALLEL per-point counting sort of edges by k (round-14).
// ---------------------------------------------------------------------------
__global__ __launch_bounds__(256)
void sort_edges_kernel(const int* __restrict__ nbr,
                       const int* __restrict__ kid,
                       const float* __restrict__ importance) {
    const int lane = threadIdx.x & 31;
    const int n    = blockIdx.x * 8 + (threadIdx.x >> 5);
    const int e0 = g_offs[n], e1 = g_offs[n + 1];
    const uint32_t ltmask = (1u << lane) - 1u;

    int off[9];
    #pragma unroll
    for (int kk = 0; kk < 9; kk++) off[kk] = 0;

    for (int base = e0; base < e1; base += 32) {
        const int e = base + lane;
        const int k = (e < e1) ? __ldg(kid + e) : 15;
        #pragma unroll
        for (int kk = 0; kk < 9; kk++)
            off[kk] += __popc(__ballot_sync(0xffffffffu, k == kk));
    }
    {
        int s = e0;
        #pragma unroll
        for (int kk = 0; kk < 9; kk++) { const int c = off[kk]; off[kk] = s; s += c; }
    }
    for (int base = e0; base < e1; base += 32) {
        const int e = base + lane;
        const bool valid = e < e1;
        const int k   = valid ? __ldg(kid + e) : 15;
        const int src = valid ? __ldg(nbr + e) : 0;
        int dst = 0;
        #pragma unroll
        for (int kk = 0; kk < 9; kk++) {
            const uint32_t m = __ballot_sync(0xffffffffu, k == kk);
            if (k == kk) dst = off[kk] + __popc(m & ltmask);
            off[kk] += __popc(m);
        }
        if (valid) {
            int2 r;
            r.x = (src << 4) | k;
            r.y = __float_as_int(__ldg(importance + src));
            g_edges[dst] = r;
        }
    }
}

// ---------------------------------------------------------------------------
// Kernel 2: compressed weights [128][576], single fp16
// ---------------------------------------------------------------------------
__global__ void build_w_kernel(const float* __restrict__ Wa,
                               const float* __restrict__ Wb) {
    int i = blockIdx.x * blockDim.x + threadIdx.x;
    if (i >= CO * KHALF) return;
    int o = i / KHALF, k = i % KHALF;
    float v = (o < 96) ? __ldg(Wa + k * 96 + o) : __ldg(Wb + k * 32 + (o - 96));
    g_B[i] = __float2half(v);
}

// ---------------------------------------------------------------------------
// Kernel 3: binning — round-14 verbatim (measured 88 us). ZERO smem; warp
// per point; lane owns channels 2l,2l+1; k-sorted edges; register k-group
// accumulation; flush fp16 directly to global staging.
// ---------------------------------------------------------------------------
__device__ __forceinline__ void flush_bins(size_t rb, int k, int lane,
                                           float2 u, float2 w) {
    const size_t off = rb + k * 64 + 2 * lane;
    __half2 hu = __floats2half2_rn(u.x, u.y);
    __half2 hw = __floats2half2_rn(w.x, w.y);
    *reinterpret_cast<uint32_t*>(&g_A[0][off]) = *reinterpret_cast<uint32_t*>(&hu);
    *reinterpret_cast<uint32_t*>(&g_A[1][off]) = *reinterpret_cast<uint32_t*>(&hw);
}

__global__ __launch_bounds__(256)
void bin_kernel(const float* __restrict__ feats,
                float*       __restrict__ out) {
    const int lane = threadIdx.x & 31;
    const int n    = blockIdx.x * 8 + (threadIdx.x >> 5);
    const int e0 = g_offs[n], e1 = g_offs[n + 1];
    const size_t rb = (size_t)n * KHALF;

    float2 u = make_float2(0.f, 0.f), w = make_float2(0.f, 0.f);
    float impacc = 0.f;
    int curk = -1;

    for (int e = e0; e < e1; e++) {
        const int2  rec = __ldg(g_edges + e);        // broadcast across warp
        const int   k   = rec.x & 15;
        const int   src = rec.x >> 4;
        const float im  = __int_as_float(rec.y);
        if (k != curk) {                              // warp-uniform branch
            if (curk >= 0) flush_bins(rb, curk, lane, u, w);
            u = make_float2(0.f, 0.f);
            w = make_float2(0.f, 0.f);
            curk = k;
        }
        const float2 f = *reinterpret_cast<const float2*>(
                             feats + (size_t)src * CIN + 2 * lane);
        u.x += f.x; u.y += f.y;
        w.x = fmaf(f.x, im, w.x);
        w.y = fmaf(f.y, im, w.y);
        impacc += im;
    }
    if (curk >= 0) flush_bins(rb, curk, lane, u, w);

    if (lane == 0) {
        g_imp[n] = impacc;
        out[(size_t)N_OUT * CO + n] = impacc;        // imp_sum output
    }
}

// ---------------------------------------------------------------------------
// Kernel 4: HMMA fp16 GEMM, SINGLE pass (pure fp16 A and B).
// 2 stages x 24KB, issue(c+1) before wait. Stage: [Au|Aw|B] x 8KB,
// 64B rows, sw64. 2 CTAs/SM. Warps 2(M64) x 4(N32); w_n<3->Au, w_n==3->Aw.
// ---------------------------------------------------------------------------
extern __shared__ __align__(128) char gsm[];

__global__ __launch_bounds__(256, 2)
void gemm_kernel(const float* __restrict__ b_a,
                 const float* __restrict__ b_b,
                 float*       __restrict__ out) {
    const int tid = threadIdx.x, lane = tid & 31, wid = tid >> 5;
    const int w_m = wid & 1, w_n = wid >> 1;
    const int g = lane >> 2, tig = lane & 3;
    const size_t mtile = (size_t)blockIdx.x * MTILE;
    const uint32_t sbase = smem_u32(gsm);

    // cp.async geometry: 2 x 16B per thread per array (128 rows x 4 cols)
    int   aIdx[2], bIdx[2];
    uint32_t dOff[2];
    #pragma unroll
    for (int q = 0; q < 2; q++) {
        const int idx = q * 256 + tid;      // 0..511
        const int row = idx >> 2, c = idx & 3;
        aIdx[q] = (int)((mtile + row) * KHALF + c * 8);
        bIdx[q] = row * KHALF + c * 8;
        dOff[q] = sw64(row * 64 + c * 16);
    }

    // ldmatrix per-lane base offsets, 64B rows
    const uint32_t aOffB = (uint32_t)(w_m * 64 + (lane & 15)) * 64
                         + ((lane >> 4) & 1) * 16;
    const uint32_t bOffB = (uint32_t)(w_n * 32 + (lane & 7) + ((lane >> 4) & 1) * 8) * 64
                         + ((lane >> 3) & 1) * 16;
    const uint32_t aSel = (w_n < 3) ? 0u : 8192u;   // Au vs Aw

    float acc[4][4][4];
    #pragma unroll
    for (int i = 0; i < 4; i++)
        #pragma unroll
        for (int j = 0; j < 4; j++)
            #pragma unroll
            for (int q = 0; q < 4; q++) acc[i][j][q] = 0.f;

    auto issue = [&](int c) {
        const uint32_t st = sbase + (uint32_t)(c & 1) * STAGE;
        const int k0 = c * KCH;
        #pragma unroll
        for (int q = 0; q < 2; q++) {
            #pragma unroll
            for (int arr = 0; arr < 2; arr++)
                cp16(st + arr * 8192 + dOff[q], &g_A[arr][0] + aIdx[q] + k0);
            cp16(st + 16384 + dOff[q], g_B + bIdx[q] + k0);
        }
        CP_COMMIT;
    };

    issue(0);

    #pragma unroll 2
    for (int c = 0; c < NCHUNK; c++) {
        if (c + 1 < NCHUNK) {
            issue(c + 1);
            asm volatile("cp.async.wait_group 1;" ::: "memory");
        } else {
            asm volatile("cp.async.wait_group 0;" ::: "memory");
        }
        __syncthreads();

        const uint32_t st = sbase + (uint32_t)(c & 1) * STAGE;
        const uint32_t sA = st + aSel;
        const uint32_t sB = st + 16384;

        #pragma unroll
        for (int ks = 0; ks < 2; ks++) {
            uint32_t bh[8];
            ldm4(bh[0], bh[1], bh[2], bh[3], sB + sw64(bOffB + ks * 32));
            ldm4(bh[4], bh[5], bh[6], bh[7], sB + sw64(bOffB + 1024 + ks * 32));
            #pragma unroll
            for (int mf = 0; mf < 4; mf++) {
                uint32_t ah[4];
                ldm4(ah[0], ah[1], ah[2], ah[3], sA + sw64(aOffB + mf * 1024 + ks * 32));
                #pragma unroll
                for (int nf = 0; nf < 4; nf++)
                    mma_f16(acc[mf][nf], ah, bh[2 * nf], bh[2 * nf + 1]);
            }
        }
        __syncthreads();
    }

    // ---- epilogue: bias / normalize / relu / store ----
    float bias[4][2];
    #pragma unroll
    for (int nf = 0; nf < 4; nf++) {
        const int col = w_n * 32 + nf * 8 + 2 * tig;
        bias[nf][0] = (col < 96) ? __ldg(b_a + col)     : __ldg(b_b + col - 96);
        bias[nf][1] = (col < 96) ? __ldg(b_a + col + 1) : __ldg(b_b + col - 95);
    }

    #pragma unroll
    for (int mf = 0; mf < 4; mf++) {
        #pragma unroll
        for (int half = 0; half < 2; half++) {
            const int n = (int)mtile + w_m * 64 + mf * 16 + g + half * 8;
            if (n >= N_OUT) continue;
            float inv = 1.f;
            if (w_n == 3) inv = 1.f / fmaxf(__ldg(g_imp + n), 1e-8f);
            #pragma unroll
            for (int nf = 0; nf < 4; nf++) {
                const int col = w_n * 32 + nf * 8 + 2 * tig;
                float2 r;
                r.x = fmaxf(fmaf(acc[mf][nf][half * 2 + 0], inv, bias[nf][0]), 0.f);
                r.y = fmaxf(fmaf(acc[mf][nf][half * 2 + 1], inv, bias[nf][1]), 0.f);
                *reinterpret_cast<float2*>(out + (size_t)n * CO + col) = r;
            }
        }
    }
}

// ---------------------------------------------------------------------------
extern "C" void kernel_launch(void* const* d_in, const int* in_sizes, int n_in,
                              void* d_out, int out_size) {
    const float* feats      = (const float*)d_in[0];
    const float* importance = (const float*)d_in[1];
    const float* W_a        = (const float*)d_in[2];
    const float* b_a        = (const float*)d_in[3];
    const float* W_b        = (const float*)d_in[4];
    const float* b_b        = (const float*)d_in[5];
    const int*   nbr        = (const int*)d_in[6];
    const int*   kid        = (const int*)d_in[7];
    const int*   oid        = (const int*)d_in[8];
    float*       out        = (float*)d_out;

    build_offsets_kernel<<<(NE + 255) / 256, 256>>>(oid);
    sort_edges_kernel<<<N_OUT / 8, 256>>>(nbr, kid, importance);
    build_w_kernel<<<(CO * KHALF + 255) / 256, 256>>>(W_a, W_b);
    bin_kernel<<<N_OUT / 8, 256>>>(feats, out);

    const int smem_bytes = 2 * STAGE;   // 49,152 B -> 2 CTAs/SM
    cudaFuncSetAttribute(gemm_kernel,
                         cudaFuncAttributeMaxDynamicSharedMemorySize, smem_bytes);
    gemm_kernel<<<NTILES, 256, smem_bytes>>>(b_a, b_b, out);
}